// round 11
// baseline (speedup 1.0000x reference)
#include <cuda_runtime.h>
#include <cuda_fp16.h>
#include <cstdint>

typedef uint32_t u32;

// ====================== problem constants ======================
constexpr int T_LEN = 4000;
constexpr int NT    = 413;
constexpr int NE    = 412;
constexpr int OFF   = 206;              // xe[u] = x_ext[u + 206]
constexpr int S_LEN = T_LEN + NT;       // 4413
constexpr int NROWS = 4096;

constexpr int KC    = 64;               // K chunk
constexpr int NCHUNK = 8;               // chunks 0..7 (chunk 8 provably all-zero B)
constexpr int XE_W  = T_LEN + 576;      // 4576
constexpr int MT    = 128;              // GEMM M (rows r)
constexpr int NTT   = 64;               // GEMM N (t positions)
constexpr int N_TTILE = (T_LEN + NTT - 1) / NTT;  // 63
constexpr int N_RBLK  = NROWS / MT;               // 32
constexpr int THREADS = 256;

constexpr float H_SCALE = 512.0f;
constexpr float INV_H_SCALE = 1.0f / 512.0f;

// A staging: 128 rows x 64 fp16, pitch 144B, 2 stages.
constexpr int PITCHB   = 144;
constexpr int STAGE_A  = 128 * PITCHB;          // 18432
constexpr int NSTAGE   = 2;
// Diagonal bank: B tile for diagonal d0 = 8t - 120, t in [0,86). 256B/tile.
constexpr int BANK_TILES = 86;
constexpr int BANK_BYTES = BANK_TILES * 256;    // 22016
constexpr int BANK_HALVES = BANK_TILES * 128;
constexpr int SMEM_DYN  = NSTAGE * STAGE_A + BANK_BYTES;   // 58880 -> 3 CTAs/SM

// band: tile t nonzero iff t in [14, 67]
constexpr int TLO = 14, THI = 67;

// ====================== device scratch ======================
__device__ __align__(16) __half g_xe[(size_t)NROWS * XE_W];
__device__ __align__(16) __half g_Bd[BANK_HALVES];

// ====================== PTX helpers (family-agnostic, sm_80+) ======================
__device__ __forceinline__ u32 smem_u32(const void* p) {
    u32 a;
    asm("{ .reg .u64 t; cvta.to.shared.u64 t, %1; cvt.u32.u64 %0, t; }" : "=r"(a) : "l"(p));
    return a;
}
#define CP_ASYNC16(dst, src) \
    asm volatile("cp.async.cg.shared.global [%0], [%1], 16;" :: "r"(dst), "l"(src))
#define CP_COMMIT() asm volatile("cp.async.commit_group;" ::: "memory")

#define LDSM4(r, addr) \
    asm volatile("ldmatrix.sync.aligned.m8n8.x4.shared.b16 {%0,%1,%2,%3}, [%4];" \
        : "=r"((r)[0]), "=r"((r)[1]), "=r"((r)[2]), "=r"((r)[3]) : "r"(addr))

#define MMA16816(d, a, b0, b1) \
    asm volatile("mma.sync.aligned.m16n8k16.row.col.f32.f16.f16.f32 " \
        "{%0,%1,%2,%3}, {%4,%5,%6,%7}, {%8,%9}, {%0,%1,%2,%3};" \
        : "+f"((d)[0]), "+f"((d)[1]), "+f"((d)[2]), "+f"((d)[3]) \
        : "r"((a)[0]), "r"((a)[1]), "r"((a)[2]), "r"((a)[3]), \
          "r"(b0), "r"(b1))

// ====================== fused prep kernel ======================
__device__ __forceinline__ float xext_val(const float* __restrict__ xr, int e) {
    if (e < NE)         return 2.0f * xr[0]         - xr[NE - e];
    if (e < NE + T_LEN) return xr[e - NE];
    return 2.0f * xr[T_LEN - 1] - xr[2 * T_LEN - 2 + NE - e];
}

__global__ void prep_kernel(const float* __restrict__ x, const float* __restrict__ h) {
    const int b = blockIdx.x;
    if (b < NROWS) {
        const float* xr = x + (size_t)b * T_LEN;
        __half* dst = g_xe + (size_t)b * XE_W;
        for (int seg = threadIdx.x; seg < XE_W / 8; seg += blockDim.x) {
            const int u0 = seg * 8;
            __half hv[8];
            #pragma unroll
            for (int q = 0; q < 8; q++) {
                int u = u0 + q;
                float v = (u < S_LEN) ? xext_val(xr, u + OFF) : 0.0f;
                hv[q] = __float2half(v);
            }
            *reinterpret_cast<uint4*>(dst + u0) = *reinterpret_cast<const uint4*>(hv);
        }
    } else {
        int idx = (b - NROWS) * blockDim.x + threadIdx.x;
        if (idx < BANK_HALVES) {
            int t  = idx >> 7;
            int r  = (idx >> 3) & 15;
            int kk = idx & 7;
            int np = r & 7;
            int kp = kk + ((r >= 8) ? 8 : 0);
            int j  = (8 * t - 120) + kp - np;       // hrev index
            float v = (j >= 0 && j < NT) ? h[NT - 1 - j] * H_SCALE : 0.0f;
            g_Bd[idx] = __float2half(v);
        }
    }
}
constexpr int PREP_BANK_BLOCKS = (BANK_HALVES + 255) / 256;   // 43

// ====================== per-chunk compute, compile-time band skip ======================
// Warp tile: 32r x 32t. Bank tile index: tb = 8C - 4WN + 12 + rel, rel = 2ks - j + 3,
// j in [0,4) (n8 tiles of the warp's 32t slice), ks in [0,4).
template<int C, int WN>
__device__ __forceinline__ void compute_chunk(u32 abase, u32 bLane, const u32* aRel,
                                              float (&acc)[2][4][4]) {
    constexpr int B0 = 8 * C - 4 * WN + 12;            // tile at rel = 0
    if constexpr (B0 + 9 < TLO || B0 > THI) return;    // whole chunk dead

    u32 bf[10][2];
    const u32 bb = bLane + (u32)(B0 * 256);
    #pragma unroll
    for (int p = 0; p < 5; p++) {
        if (B0 + 2 * p + 1 >= TLO && B0 + 2 * p <= THI) {
            u32 r4[4];
            LDSM4(r4, bb + p * 512);
            bf[2*p][0]   = r4[0]; bf[2*p][1]   = r4[1];
            bf[2*p+1][0] = r4[2]; bf[2*p+1][1] = r4[3];
        }
    }
    #pragma unroll
    for (int ks = 0; ks < 4; ks++) {
        // surviving j? rel in [2ks, 2ks+3] -> tb in [B0+2ks, B0+2ks+3]
        if (B0 + 2 * ks + 3 >= TLO && B0 + 2 * ks <= THI) {
            u32 a[2][4];
            #pragma unroll
            for (int i = 0; i < 2; i++)
                LDSM4(a[i], abase + aRel[i] + ks * 32);
            #pragma unroll
            for (int i = 0; i < 2; i++)
                #pragma unroll
                for (int j = 0; j < 4; j++) {
                    const int tb = B0 + 2 * ks - j + 3;
                    if (tb >= TLO && tb <= THI)
                        MMA16816(acc[i][j], a[i], bf[2*ks - j + 3][0], bf[2*ks - j + 3][1]);
                }
        }
    }
}

// ====================== GEMM kernel ======================
__global__ void __launch_bounds__(THREADS, 3)
fir_gemm_kernel(float* __restrict__ out) {
    extern __shared__ __align__(1024) char smem[];
    const int tid = threadIdx.x;
    const int wid = tid >> 5;
    const int lid = tid & 31;
    const int wm  = wid & 3;        // row slice of 32
    const int wn  = wid >> 2;       // t slice of 32 (0..1)
    const int t0    = blockIdx.x * NTT;
    const int rbase = blockIdx.y * MT;

    const u32 sb   = smem_u32(smem);
    const u32 bank = sb + NSTAGE * STAGE_A;

    // ---- A staging addresses (4 x 16B per thread per chunk) ----
    const char* xebase = (const char*)g_xe;
    u32 asrc[4], adst[4];
    #pragma unroll
    for (int it = 0; it < 4; it++) {
        int idx = it * THREADS + tid;   // 0..1023
        int r = idx >> 3, seg = idx & 7;
        asrc[it] = (u32)(((size_t)(rbase + r) * XE_W + t0 + seg * 8) * 2);
        adst[it] = r * PITCHB + seg * 16;
    }
    auto stageA = [&](int c, u32 dbase) {
        const int koff = c * 128;
        #pragma unroll
        for (int it = 0; it < 4; it++)
            CP_ASYNC16(dbase + adst[it], xebase + asrc[it] + koff);
    };

    // ---- one-time bank load + first A stage (one group) ----
    {
        const char* bdbase = (const char*)g_Bd;
        for (int i = tid; i < BANK_BYTES / 16; i += THREADS)
            CP_ASYNC16(bank + i * 16, bdbase + (size_t)i * 16);
    }
    stageA(0, sb);
    CP_COMMIT();

    // ---- ldmatrix bases ----
    u32 aRel[2];
    #pragma unroll
    for (int i = 0; i < 2; i++)
        aRel[i] = (wm * 32 + i * 16 + (lid & 15)) * PITCHB + ((lid >> 4) * 16);
    const u32 bLane = bank + lid * 16;

    float acc[2][4][4];
    #pragma unroll
    for (int i = 0; i < 2; i++)
        #pragma unroll
        for (int j = 0; j < 4; j++)
            #pragma unroll
            for (int q = 0; q < 4; q++) acc[i][j][q] = 0.0f;

    // ---- unrolled chunk loop: 2-stage ring, distance-1 prefetch, 1 barrier/chunk ----
#define GSTEP(C)                                                                         \
    do {                                                                                 \
        asm volatile("cp.async.wait_group 0;" ::: "memory");                             \
        __syncthreads();  /* chunk C visible; buffer (C+1)%2's readers (chunk C-1) done */ \
        if ((C) + 1 < NCHUNK) {                                                          \
            stageA((C) + 1, sb + (((C) + 1) & 1) * STAGE_A);                             \
            CP_COMMIT();                                                                 \
        }                                                                                \
        const u32 abase_ = sb + ((C) & 1) * STAGE_A;                                     \
        if (wn == 0) compute_chunk<(C), 0>(abase_, bLane, aRel, acc);                    \
        else         compute_chunk<(C), 1>(abase_, bLane, aRel, acc);                    \
    } while (0)

    GSTEP(0); GSTEP(1); GSTEP(2); GSTEP(3);
    GSTEP(4); GSTEP(5); GSTEP(6); GSTEP(7);
#undef GSTEP

    // ---- epilogue: D[m=r][n=t] -> out[r*T_LEN + t], undo H_SCALE ----
    #pragma unroll
    for (int i = 0; i < 2; i++) {
        int r0 = rbase + wm * 32 + i * 16 + (lid >> 2);
        #pragma unroll
        for (int j = 0; j < 4; j++) {
            int t = t0 + wn * 32 + j * 8 + 2 * (lid & 3);
            if (t < T_LEN) {
                *reinterpret_cast<float2*>(out + (size_t)r0 * T_LEN + t) =
                    make_float2(acc[i][j][0] * INV_H_SCALE, acc[i][j][1] * INV_H_SCALE);
                *reinterpret_cast<float2*>(out + (size_t)(r0 + 8) * T_LEN + t) =
                    make_float2(acc[i][j][2] * INV_H_SCALE, acc[i][j][3] * INV_H_SCALE);
            }
        }
    }
}

// ====================== launch ======================
extern "C" void kernel_launch(void* const* d_in, const int* in_sizes, int n_in,
                              void* d_out, int out_size)
{
    const float* x = (const float*)d_in[0];   // [64, 64, 4000] f32
    const float* h = (const float*)d_in[1];   // [413] f32
    float* out = (float*)d_out;

    cudaFuncSetAttribute(fir_gemm_kernel,
                         cudaFuncAttributeMaxDynamicSharedMemorySize, SMEM_DYN);

    prep_kernel<<<NROWS + PREP_BANK_BLOCKS, 256>>>(x, h);
    fir_gemm_kernel<<<dim3(N_TTILE, N_RBLK), THREADS, SMEM_DYN>>>(out);
}